// round 4
// baseline (speedup 1.0000x reference)
#include <cuda_runtime.h>
#include <math.h>

#define HIDDEN 512
#define H4     (HIDDEN / 4)
#define BATCH  4096
#define BN_EPS 1e-5f

// ---------------- scratch (device globals; no allocations allowed) ----------
__device__ float4 g_pooled[BATCH * H4];   // [4096, 512] mean-pooled embeddings
__device__ float4 g_h[BATCH * H4];        // [4096, 512] hidden pre-BN
__device__ float  g_colsum[HIDDEN];
__device__ float  g_colsq[HIDDEN];
__device__ float  g_mu[HIDDEN];
__device__ float  g_istd[HIDDEN];
__device__ float  g_loss;

// ---------------- kernel 0: zero per-launch accumulators --------------------
__global__ void zero_kernel() {
    int i = blockIdx.x * blockDim.x + threadIdx.x;
    if (i < HIDDEN) { g_colsum[i] = 0.f; g_colsq[i] = 0.f; }
    if (i == 0) g_loss = 0.f;
}

// ---------------- kernel 1: ragged gather + mean pool -----------------------
// One block per segment (segment_ids is sorted). 128 threads; each thread owns
// 4 contiguous hidden dims (one float4 lane of the 2KB row). Tokens staged
// through shared memory; dual accumulators for deeper load pipelining.
__global__ __launch_bounds__(128) void pool_kernel(const int* __restrict__ tokens,
                                                   const int* __restrict__ seg,
                                                   const float* __restrict__ emb,
                                                   int T) {
    int b = blockIdx.x;
    // lower_bound(b)
    int lo = 0, hi = T;
    while (lo < hi) { int m = (lo + hi) >> 1; if (seg[m] < b) lo = m + 1; else hi = m; }
    int start = lo;
    // upper_bound(b), continuing from lower bound
    hi = T;
    while (lo < hi) { int m = (lo + hi) >> 1; if (seg[m] <= b) lo = m + 1; else hi = m; }
    int end = lo;

    const int t = threadIdx.x;                      // 0..127
    const float4* __restrict__ embv = (const float4*)emb;
    float4 acc0 = make_float4(0.f, 0.f, 0.f, 0.f);
    float4 acc1 = make_float4(0.f, 0.f, 0.f, 0.f);

    __shared__ int stok[256];   // broadcast reads (all lanes same addr) -> no conflicts
    for (int base = start; base < end; base += 256) {
        int n = min(256, end - base);
        if (t < n)        stok[t]       = tokens[base + t];
        if (t + 128 < n)  stok[t + 128] = tokens[base + t + 128];
        __syncthreads();
        int r = 0;
        // paired iterations: 2 independent in-flight loads per thread per step,
        // unrolled x4 -> up to 8 outstanding LDG.128s per thread
        #pragma unroll 4
        for (; r + 2 <= n; r += 2) {
            long i0 = (long)stok[r]     * H4 + t;
            long i1 = (long)stok[r + 1] * H4 + t;
            float4 v0 = __ldg(&embv[i0]);
            float4 v1 = __ldg(&embv[i1]);
            acc0.x += v0.x; acc0.y += v0.y; acc0.z += v0.z; acc0.w += v0.w;
            acc1.x += v1.x; acc1.y += v1.y; acc1.z += v1.z; acc1.w += v1.w;
        }
        if (r < n) {
            float4 v = __ldg(&embv[(long)stok[r] * H4 + t]);
            acc0.x += v.x; acc0.y += v.y; acc0.z += v.z; acc0.w += v.w;
        }
        __syncthreads();
    }
    float invc = 1.f / fmaxf((float)(end - start), 1.f);
    float4 acc;
    acc.x = (acc0.x + acc1.x) * invc;
    acc.y = (acc0.y + acc1.y) * invc;
    acc.z = (acc0.z + acc1.z) * invc;
    acc.w = (acc0.w + acc1.w) * invc;
    g_pooled[b * H4 + t] = acc;
}

// ---------------- kernel 2: h = pooled @ W_h + b_h --------------------------
// M=4096, N=512, K=512. 64x64 tile per block, BK=16, 256 threads, 4x4/thread.
__global__ __launch_bounds__(256) void gemm_kernel(const float* __restrict__ Bw,   // W_h [K,N]
                                                   const float* __restrict__ bias) {
    const int N = HIDDEN, K = HIDDEN;
    __shared__ float As[16][64];   // [k][m]
    __shared__ float Bs[16][64];   // [k][n]

    const float* A = (const float*)g_pooled;   // [M,K]
    float*       C = (float*)g_h;              // [M,N]

    int bx = blockIdx.x;   // N tile (0..7)
    int by = blockIdx.y;   // M tile (0..63)
    int tid = threadIdx.x;
    int tx = tid & 15;     // 0..15 -> n
    int ty = tid >> 4;     // 0..15 -> m

    // A-tile loader coords: 64 rows x 16 k, float4 per thread
    int aRow = tid >> 2;          // 0..63
    int aCol = (tid & 3) * 4;     // 0,4,8,12
    // B-tile loader coords: 16 k x 64 n, float4 per thread
    int bRow = tid >> 4;          // 0..15
    int bCol = (tid & 15) * 4;    // 0..60

    float acc[4][4];
    #pragma unroll
    for (int i = 0; i < 4; i++)
        #pragma unroll
        for (int j = 0; j < 4; j++) acc[i][j] = 0.f;

    for (int k0 = 0; k0 < K; k0 += 16) {
        float4 av = *(const float4*)&A[(size_t)(by * 64 + aRow) * K + k0 + aCol];
        As[aCol + 0][aRow] = av.x;
        As[aCol + 1][aRow] = av.y;
        As[aCol + 2][aRow] = av.z;
        As[aCol + 3][aRow] = av.w;
        float4 bv = *(const float4*)&Bw[(size_t)(k0 + bRow) * N + bx * 64 + bCol];
        *(float4*)&Bs[bRow][bCol] = bv;
        __syncthreads();

        #pragma unroll
        for (int kk = 0; kk < 16; kk++) {
            float ra[4], rb[4];
            #pragma unroll
            for (int i = 0; i < 4; i++) ra[i] = As[kk][ty * 4 + i];
            #pragma unroll
            for (int j = 0; j < 4; j++) rb[j] = Bs[kk][tx * 4 + j];
            #pragma unroll
            for (int i = 0; i < 4; i++)
                #pragma unroll
                for (int j = 0; j < 4; j++)
                    acc[i][j] = fmaf(ra[i], rb[j], acc[i][j]);
        }
        __syncthreads();
    }

    #pragma unroll
    for (int i = 0; i < 4; i++) {
        int row = by * 64 + ty * 4 + i;
        #pragma unroll
        for (int j = 0; j < 4; j++) {
            int col = bx * 64 + tx * 4 + j;
            C[(size_t)row * N + col] = acc[i][j] + bias[col];
        }
    }
}

// ---------------- kernel 3: column sums for batch stats ---------------------
// 128 blocks x 512 threads; block handles 32 rows; thread j owns column j.
__global__ void stats_kernel() {
    const float* h = (const float*)g_h;
    int j = threadIdx.x;
    int r0 = blockIdx.x * 32;
    float s = 0.f, sq = 0.f;
    #pragma unroll 8
    for (int r = r0; r < r0 + 32; r++) {
        float v = h[(size_t)r * HIDDEN + j];
        s += v; sq += v * v;
    }
    atomicAdd(&g_colsum[j], s);
    atomicAdd(&g_colsq[j], sq);
}

// ---------------- kernel 4: finalize mu / inv_std ---------------------------
__global__ void finalize_stats_kernel() {
    int j = threadIdx.x;
    float mu = g_colsum[j] * (1.f / BATCH);
    float var = g_colsq[j] * (1.f / BATCH) - mu * mu;
    g_mu[j] = mu;
    g_istd[j] = rsqrtf(var + BN_EPS);
}

// ---------------- kernel 5: BN + ReLU + dot(W_o) + BCE ----------------------
// One block per row, 128 threads, 4 cols each.
__global__ void logits_kernel(const float* __restrict__ t,
                              const float* __restrict__ gamma,
                              const float* __restrict__ beta,
                              const float* __restrict__ W_o,
                              const float* __restrict__ b_o,
                              float* __restrict__ out_logits) {
    int i = blockIdx.x;
    int tdx = threadIdx.x;
    const float4* hv    = &g_h[i * H4];
    const float4* muv   = (const float4*)g_mu;
    const float4* isv   = (const float4*)g_istd;
    const float4* gv    = (const float4*)gamma;
    const float4* bev   = (const float4*)beta;
    const float4* wv    = (const float4*)W_o;

    float4 h = hv[tdx], mu = muv[tdx], is = isv[tdx],
           ga = gv[tdx], be = bev[tdx], w = wv[tdx];
    float a0 = fmaxf(ga.x * (h.x - mu.x) * is.x + be.x, 0.f);
    float a1 = fmaxf(ga.y * (h.y - mu.y) * is.y + be.y, 0.f);
    float a2 = fmaxf(ga.z * (h.z - mu.z) * is.z + be.z, 0.f);
    float a3 = fmaxf(ga.w * (h.w - mu.w) * is.w + be.w, 0.f);
    float acc = a0 * w.x + a1 * w.y + a2 * w.z + a3 * w.w;

    // warp reduce
    #pragma unroll
    for (int off = 16; off > 0; off >>= 1)
        acc += __shfl_xor_sync(0xffffffff, acc, off);
    __shared__ float warpsum[4];
    if ((tdx & 31) == 0) warpsum[tdx >> 5] = acc;
    __syncthreads();
    if (tdx == 0) {
        float logit = warpsum[0] + warpsum[1] + warpsum[2] + warpsum[3] + b_o[0];
        if (out_logits) out_logits[i] = logit;
        // softplus(x) - t*x, numerically stable softplus
        float sp = fmaxf(logit, 0.f) + log1pf(expf(-fabsf(logit)));
        atomicAdd(&g_loss, (sp - t[i] * logit) * (1.f / BATCH));
    }
}

// ---------------- kernel 6: write loss ---------------------------------------
__global__ void write_loss_kernel(float* __restrict__ out_loss) {
    if (out_loss) out_loss[0] = g_loss;
}

// ---------------- launch ------------------------------------------------------
extern "C" void kernel_launch(void* const* d_in, const int* in_sizes, int n_in,
                              void* d_out, int out_size) {
    const int*   tokens = (const int*)d_in[0];
    const int*   seg    = (const int*)d_in[1];
    const float* t      = (const float*)d_in[2];
    const float* emb    = (const float*)d_in[3];
    const float* W_h    = (const float*)d_in[4];
    const float* b_h    = (const float*)d_in[5];
    const float* gamma  = (const float*)d_in[6];
    const float* beta   = (const float*)d_in[7];
    const float* W_o    = (const float*)d_in[8];
    const float* b_o    = (const float*)d_in[9];
    const int T = in_sizes[0];

    float* out = (float*)d_out;
    float* out_loss = nullptr;
    float* out_logits = nullptr;
    if (out_size >= BATCH + 1) { out_loss = out; out_logits = out + 1; }
    else if (out_size == BATCH) { out_logits = out; }
    else { out_loss = out; }

    zero_kernel<<<2, 512>>>();
    pool_kernel<<<BATCH, 128>>>(tokens, seg, emb, T);
    {
        dim3 grid(HIDDEN / 64, BATCH / 64);
        gemm_kernel<<<grid, 256>>>(W_h, b_h);
    }
    stats_kernel<<<BATCH / 32, HIDDEN>>>();
    finalize_stats_kernel<<<1, HIDDEN>>>();
    logits_kernel<<<BATCH, 128>>>(t, gamma, beta, W_o, b_o, out_logits);
    write_loss_kernel<<<1, 1>>>(out_loss);
}